// round 9
// baseline (speedup 1.0000x reference)
#include <cuda_runtime.h>

#define NN 200000
#define NE 6400000
#define FIN 128
#define HID 16
#define CAP 96    // fixed bucket capacity; max degree ~60 (Binomial mean 32, sd 5.7)

// ---- scratch (device globals; no allocation allowed) ----
// INVARIANT across graph replays: g_cnt == 0 on entry
// (static zero-init on call 1; gather2_kernel re-zeros it each call).
__device__ __align__(16) float g_h[NN * HID];              // layer-1 transformed features
__device__ __align__(16) float g_h2[NN * HID];             // layer-2 transformed features
__device__ int g_cnt[NN];                                  // per-node in-degree / cursor
__device__ unsigned long long g_edges[(size_t)NN * CAP];   // bucketed (src:int, w:float)

// ---------------------------------------------------------------------------
// K0: bucket placement. pos = atomicAdd(cnt[d]); edges[d*CAP+pos] = (src, w).
// Default (write-back) stores so the bucket array stays L2-resident for the
// gather passes. Streaming inputs use __ldcs (read once).
// ---------------------------------------------------------------------------
__global__ void edge_place_kernel(const int* __restrict__ src,
                                  const int* __restrict__ dst,
                                  const float* __restrict__ w,
                                  int* __restrict__ cnt,
                                  unsigned long long* __restrict__ edges) {
    int e = blockIdx.x * blockDim.x + threadIdx.x;
    if (e >= NE) return;
    int d = __ldcs(dst + e);
    int pos = atomicAdd(&cnt[d], 1);
    if (pos < CAP) {
        unsigned long long pk = (unsigned long long)(unsigned)__ldcs(src + e) |
                                ((unsigned long long)__float_as_uint(__ldcs(w + e)) << 32);
        edges[(size_t)d * CAP + pos] = pk;           // write-back: stay in L2
    }
}

// ---------------------------------------------------------------------------
// K1: h1pre = x @ W1   (N x 128 @ 128 x 16), warp per node.
// ---------------------------------------------------------------------------
__global__ void gemm1_kernel(const float* __restrict__ x,
                             const float* __restrict__ W1,
                             float* __restrict__ out) {
    __shared__ __align__(16) float sWt[HID * FIN];
    for (int i = threadIdx.x; i < HID * FIN; i += blockDim.x) {
        int j = i / FIN, k = i % FIN;
        sWt[i] = W1[k * HID + j];
    }
    __syncthreads();

    int gwarp = (blockIdx.x * blockDim.x + threadIdx.x) >> 5;
    int lane  = threadIdx.x & 31;
    if (gwarp >= NN) return;

    float4 xv = __ldcs(((const float4*)(x + (size_t)gwarp * FIN)) + lane);

    float acc[HID];
    const float4* sWt4 = (const float4*)sWt;
#pragma unroll
    for (int j = 0; j < HID; j++) {
        float4 wv = sWt4[j * (FIN / 4) + lane];
        acc[j] = xv.x * wv.x + xv.y * wv.y + xv.z * wv.z + xv.w * wv.w;
    }
#pragma unroll
    for (int j = 0; j < HID; j++) {
#pragma unroll
        for (int off = 16; off; off >>= 1)
            acc[j] += __shfl_xor_sync(0xFFFFFFFFu, acc[j], off);
    }
    if (lane < HID) out[(size_t)gwarp * HID + lane] = acc[lane];
}

// ---------------------------------------------------------------------------
// Warp-level gather core: 8 slots x 4 chunk lanes, TWO-deep rotating edge
// prefetch (record for iter k+2 in flight while consuming iter k), so even a
// DRAM-latency edge miss is overlapped. All loads default-cached (__ldg).
// ---------------------------------------------------------------------------
__device__ __forceinline__ float4 gather_accum(const unsigned long long* __restrict__ edges,
                                               const float* __restrict__ h,
                                               size_t start, int deg,
                                               int j, int slot) {
    float4 acc = make_float4(0.f, 0.f, 0.f, 0.f);
    int i = slot;
    if (i >= deg) return acc;
    unsigned long long pk = __ldg(edges + start + i);
    int inext = i + 8;
    unsigned long long pknext = (inext < deg) ? __ldg(edges + start + inext) : 0ull;
    while (true) {
        int inn = inext + 8;
        unsigned long long pknn = (inn < deg) ? __ldg(edges + start + inn) : 0ull;

        float we = __uint_as_float((unsigned)(pk >> 32));
        float4 v = __ldg((const float4*)(h + (size_t)(unsigned)pk * HID) + j);
        acc.x += we * v.x; acc.y += we * v.y; acc.z += we * v.z; acc.w += we * v.w;

        if (inext >= deg) break;
        pk = pknext; pknext = pknn; inext = inn;
    }
    return acc;
}

// ---------------------------------------------------------------------------
// K2: gather pass 1. agg = sum_e w_e*h[src_e]; out = relu(agg+b1) @ W2.
// ---------------------------------------------------------------------------
__global__ void gather1_kernel(const unsigned long long* __restrict__ edges,
                               const int* __restrict__ cnt,
                               const float* __restrict__ h,
                               const float* __restrict__ b1,
                               const float* __restrict__ W2,
                               float* __restrict__ out) {
    __shared__ __align__(16) float sW[HID * HID];
    __shared__ float sb[HID];
    __shared__ __align__(16) float sa[8][HID];     // 8 warps/block
    for (int i = threadIdx.x; i < HID * HID; i += blockDim.x) sW[i] = W2[i];
    if (threadIdx.x < HID) sb[threadIdx.x] = b1[threadIdx.x];
    __syncthreads();

    int n    = (blockIdx.x * blockDim.x + threadIdx.x) >> 5;   // exact: NN % 8 == 0
    int lane = threadIdx.x & 31;
    int wloc = threadIdx.x >> 5;
    int j    = lane & 3;
    int slot = lane >> 2;

    int deg = min(__ldg(cnt + n), CAP);
    float4 acc = gather_accum(edges, h, (size_t)n * CAP, deg, j, slot);

    // reduce across the 8 slots holding the same chunk j (lanes stride 4)
#pragma unroll
    for (int off = 4; off < 32; off <<= 1) {
        acc.x += __shfl_xor_sync(0xFFFFFFFFu, acc.x, off);
        acc.y += __shfl_xor_sync(0xFFFFFFFFu, acc.y, off);
        acc.z += __shfl_xor_sync(0xFFFFFFFFu, acc.z, off);
        acc.w += __shfl_xor_sync(0xFFFFFFFFu, acc.w, off);
    }
    if (lane < 4) *(float4*)&sa[wloc][4 * lane] = acc;   // lane == its chunk j
    __syncwarp();

    if (lane < HID) {
        float o = 0.f;
#pragma unroll
        for (int k = 0; k < HID; k++) {
            float a = fmaxf(sa[wloc][k] + sb[k], 0.f);
            o += a * sW[k * HID + lane];
        }
        out[(size_t)n * HID + lane] = o;
    }
}

// ---------------------------------------------------------------------------
// K3: gather pass 2. out = relu(agg2+b2)@Wd+bd. Re-zeros cnt for next replay.
// ---------------------------------------------------------------------------
__global__ void gather2_kernel(const unsigned long long* __restrict__ edges,
                               int* __restrict__ cnt,
                               const float* __restrict__ h,
                               const float* __restrict__ b2,
                               const float* __restrict__ Wd,
                               const float* __restrict__ bd,
                               float* __restrict__ out) {
    __shared__ float sb[HID], sw[HID];
    __shared__ float sbd;
    __shared__ __align__(16) float sa[8][HID];
    if (threadIdx.x < HID) { sb[threadIdx.x] = b2[threadIdx.x]; sw[threadIdx.x] = Wd[threadIdx.x]; }
    if (threadIdx.x == 0) sbd = bd[0];
    __syncthreads();

    int n    = (blockIdx.x * blockDim.x + threadIdx.x) >> 5;
    int lane = threadIdx.x & 31;
    int wloc = threadIdx.x >> 5;
    int j    = lane & 3;
    int slot = lane >> 2;

    int deg = min(cnt[n], CAP);
    if (lane == 0) cnt[n] = 0;          // restore invariant for next replay

    float4 acc = gather_accum(edges, h, (size_t)n * CAP, deg, j, slot);

#pragma unroll
    for (int off = 4; off < 32; off <<= 1) {
        acc.x += __shfl_xor_sync(0xFFFFFFFFu, acc.x, off);
        acc.y += __shfl_xor_sync(0xFFFFFFFFu, acc.y, off);
        acc.z += __shfl_xor_sync(0xFFFFFFFFu, acc.z, off);
        acc.w += __shfl_xor_sync(0xFFFFFFFFu, acc.w, off);
    }
    if (lane < 4) *(float4*)&sa[wloc][4 * lane] = acc;
    __syncwarp();

    if (lane == 0) {
        float o = sbd;
#pragma unroll
        for (int k = 0; k < HID; k++)
            o += fmaxf(sa[wloc][k] + sb[k], 0.f) * sw[k];
        out[n] = o;
    }
}

// ---------------------------------------------------------------------------
extern "C" void kernel_launch(void* const* d_in, const int* in_sizes, int n_in,
                              void* d_out, int out_size) {
    const float* x   = (const float*)d_in[0];
    const int*   src = (const int*)d_in[1];
    const int*   dst = (const int*)d_in[2];
    const float* ew  = (const float*)d_in[3];
    const float* W1  = (const float*)d_in[4];
    const float* b1  = (const float*)d_in[5];
    const float* W2  = (const float*)d_in[6];
    const float* b2  = (const float*)d_in[7];
    const float* Wd  = (const float*)d_in[8];
    const float* bd  = (const float*)d_in[9];
    float* out = (float*)d_out;

    float *hP, *h2P;
    int *cntP;
    unsigned long long *edgP;
    cudaGetSymbolAddress((void**)&hP,   g_h);
    cudaGetSymbolAddress((void**)&h2P,  g_h2);
    cudaGetSymbolAddress((void**)&cntP, g_cnt);
    cudaGetSymbolAddress((void**)&edgP, g_edges);

    const int TPB = 256;
    const int edge_blocks  = (NE + TPB - 1) / TPB;         // 25000
    const int gemm1_blocks = (NN * 32 + TPB - 1) / TPB;    // 25000, warp per node
    const int warp_blocks  = NN / (TPB / 32);              // 25000, exact

    // K0: single-kernel bucket build (cnt assumed zero; gather2 restores it)
    edge_place_kernel<<<edge_blocks, TPB>>>(src, dst, ew, cntP, edgP);
    // K1: feature transform
    gemm1_kernel<<<gemm1_blocks, TPB>>>(x, W1, hP);
    // K2: layer-1 gather + fused relu/b1/@W2 -> g_h2
    gather1_kernel<<<warp_blocks, TPB>>>(edgP, cntP, hP, b1, W2, h2P);
    // K3: layer-2 gather + fused relu/b2/@Wd+bd -> out; re-zeros cnt
    gather2_kernel<<<warp_blocks, TPB>>>(edgP, cntP, h2P, b2, Wd, bd, out);
}

// round 10
// speedup vs baseline: 1.3996x; 1.3996x over previous
#include <cuda_runtime.h>

#define NN 200000
#define NE 6400000
#define FIN 128
#define HID 16

// ---- scratch (device globals; no allocation allowed) ----
// INVARIANT across graph replays: g_agg == 0 on entry.
// (static zero-init on call 1; mid_kernel re-zeros after pass-1 read,
//  final_kernel re-zeros after pass-2 read.)
__device__ __align__(16) float g_h[NN * HID];    // layer input features (h1pre, then h2pre)
__device__ __align__(16) float g_agg[NN * HID];  // scatter-add accumulator (both layers)

// ---------------------------------------------------------------------------
// K0: h1pre = x @ W1   (N x 128 @ 128 x 16), warp per node.
// ---------------------------------------------------------------------------
__global__ void gemm1_kernel(const float* __restrict__ x,
                             const float* __restrict__ W1,
                             float* __restrict__ out) {
    __shared__ __align__(16) float sWt[HID * FIN];
    for (int i = threadIdx.x; i < HID * FIN; i += blockDim.x) {
        int j = i / FIN, k = i % FIN;
        sWt[i] = W1[k * HID + j];
    }
    __syncthreads();

    int gwarp = (blockIdx.x * blockDim.x + threadIdx.x) >> 5;
    int lane  = threadIdx.x & 31;
    if (gwarp >= NN) return;

    float4 xv = __ldcs(((const float4*)(x + (size_t)gwarp * FIN)) + lane);

    float acc[HID];
    const float4* sWt4 = (const float4*)sWt;
#pragma unroll
    for (int j = 0; j < HID; j++) {
        float4 wv = sWt4[j * (FIN / 4) + lane];
        acc[j] = xv.x * wv.x + xv.y * wv.y + xv.z * wv.z + xv.w * wv.w;
    }
#pragma unroll
    for (int j = 0; j < HID; j++) {
#pragma unroll
        for (int off = 16; off; off >>= 1)
            acc[j] += __shfl_xor_sync(0xFFFFFFFFu, acc[j], off);
    }
    if (lane < HID) out[(size_t)gwarp * HID + lane] = acc[lane];
}

// ---------------------------------------------------------------------------
// Edge scatter: agg[dst] += w * h[src].  4 lanes per edge (lanes 4e..4e+3
// handle edge e's four float4 chunks): warp instruction = 8 edges x 64B
// contiguous -> minimal sector count for gather and RED.
// Streaming inputs via __ldcs so they don't evict h/agg from L2.
// ---------------------------------------------------------------------------
__global__ void scatter4_kernel(const int* __restrict__ src,
                                const int* __restrict__ dst,
                                const float* __restrict__ w,
                                const float* __restrict__ h,
                                float* __restrict__ agg) {
    long long t = (long long)blockIdx.x * blockDim.x + threadIdx.x;
    int e = (int)(t >> 2);
    int j = (int)(t & 3);
    if (e >= NE) return;

    int   s  = __ldcs(src + e);   // 4-lane broadcast within warp
    int   d  = __ldcs(dst + e);
    float we = __ldcs(w + e);

    float4 v = __ldg((const float4*)(h + (size_t)s * HID) + j);
    v.x *= we; v.y *= we; v.z *= we; v.w *= we;

    float* ad = agg + (size_t)d * HID + 4 * j;
    asm volatile(
        "red.global.add.v4.f32 [%0], {%1, %2, %3, %4};"
        :: "l"(ad), "f"(v.x), "f"(v.y), "f"(v.z), "f"(v.w)
        : "memory");
}

// ---------------------------------------------------------------------------
// K2: h2pre = relu(agg + b1) @ W2 ; RESETS agg to zero for pass 2.
// ---------------------------------------------------------------------------
__global__ void mid_kernel(float* __restrict__ agg,
                           const float* __restrict__ b1,
                           const float* __restrict__ W2,
                           float* __restrict__ out) {
    __shared__ __align__(16) float sW[HID * HID];
    __shared__ float sb[HID];
    for (int i = threadIdx.x; i < HID * HID; i += blockDim.x) sW[i] = W2[i];
    if (threadIdx.x < HID) sb[threadIdx.x] = b1[threadIdx.x];
    __syncthreads();

    int n = blockIdx.x * blockDim.x + threadIdx.x;
    if (n >= NN) return;

    float a[HID];
    float4* ap = (float4*)(agg + (size_t)n * HID);
#pragma unroll
    for (int i = 0; i < 4; i++) {
        float4 v = ap[i];
        a[4 * i + 0] = v.x; a[4 * i + 1] = v.y;
        a[4 * i + 2] = v.z; a[4 * i + 3] = v.w;
    }
    // reset for the next scatter pass (fused zero)
#pragma unroll
    for (int i = 0; i < 4; i++) ap[i] = make_float4(0.f, 0.f, 0.f, 0.f);

#pragma unroll
    for (int k = 0; k < HID; k++) a[k] = fmaxf(a[k] + sb[k], 0.f);

    float o[HID];
#pragma unroll
    for (int j = 0; j < HID; j++) {
        float acc = 0.f;
#pragma unroll
        for (int k = 0; k < HID; k++) acc += a[k] * sW[k * HID + j];
        o[j] = acc;
    }
    float4* op = (float4*)(out + (size_t)n * HID);
#pragma unroll
    for (int i = 0; i < 4; i++)
        op[i] = make_float4(o[4 * i], o[4 * i + 1], o[4 * i + 2], o[4 * i + 3]);
}

// ---------------------------------------------------------------------------
// K4: out = relu(agg + b2) @ Wd + bd ; RESETS agg to zero for next replay.
// ---------------------------------------------------------------------------
__global__ void final_kernel(float* __restrict__ agg,
                             const float* __restrict__ b2,
                             const float* __restrict__ Wd,
                             const float* __restrict__ bd,
                             float* __restrict__ out) {
    __shared__ float sb[HID], sw[HID], sbd;
    if (threadIdx.x < HID) { sb[threadIdx.x] = b2[threadIdx.x]; sw[threadIdx.x] = Wd[threadIdx.x]; }
    if (threadIdx.x == 0) sbd = bd[0];
    __syncthreads();

    int n = blockIdx.x * blockDim.x + threadIdx.x;
    if (n >= NN) return;

    float4* ap = (float4*)(agg + (size_t)n * HID);
    float acc = sbd;
#pragma unroll
    for (int i = 0; i < 4; i++) {
        float4 v = ap[i];
        acc += fmaxf(v.x + sb[4 * i + 0], 0.f) * sw[4 * i + 0];
        acc += fmaxf(v.y + sb[4 * i + 1], 0.f) * sw[4 * i + 1];
        acc += fmaxf(v.z + sb[4 * i + 2], 0.f) * sw[4 * i + 2];
        acc += fmaxf(v.w + sb[4 * i + 3], 0.f) * sw[4 * i + 3];
    }
    // restore invariant for the next replay
#pragma unroll
    for (int i = 0; i < 4; i++) ap[i] = make_float4(0.f, 0.f, 0.f, 0.f);

    out[n] = acc;
}

// ---------------------------------------------------------------------------
extern "C" void kernel_launch(void* const* d_in, const int* in_sizes, int n_in,
                              void* d_out, int out_size) {
    const float* x   = (const float*)d_in[0];
    const int*   src = (const int*)d_in[1];
    const int*   dst = (const int*)d_in[2];
    const float* ew  = (const float*)d_in[3];
    const float* W1  = (const float*)d_in[4];
    const float* b1  = (const float*)d_in[5];
    const float* W2  = (const float*)d_in[6];
    const float* b2  = (const float*)d_in[7];
    const float* Wd  = (const float*)d_in[8];
    const float* bd  = (const float*)d_in[9];
    float* out = (float*)d_out;

    float *hP, *aggP;
    cudaGetSymbolAddress((void**)&hP,   g_h);
    cudaGetSymbolAddress((void**)&aggP, g_agg);

    const int TPB = 256;
    const int gemm1_blocks = (NN * 32 + TPB - 1) / TPB;        // warp per node
    const long long scat_threads = (long long)NE * 4;          // 4 lanes per edge
    const int scat_blocks  = (int)((scat_threads + TPB - 1) / TPB);
    const int node_blocks  = (NN + TPB - 1) / TPB;

    // K0: feature transform (agg already zero by invariant)
    gemm1_kernel<<<gemm1_blocks, TPB>>>(x, W1, hP);
    // K1: layer-1 scatter
    scatter4_kernel<<<scat_blocks, TPB>>>(src, dst, ew, hP, aggP);
    // K2: relu(agg+b1)@W2 -> h ; re-zeros agg
    mid_kernel<<<node_blocks, TPB>>>(aggP, b1, W2, hP);
    // K3 (profiled): layer-2 scatter
    scatter4_kernel<<<scat_blocks, TPB>>>(src, dst, ew, hP, aggP);
    // K4: relu(agg+b2)@Wd+bd -> out ; re-zeros agg for next replay
    final_kernel<<<node_blocks, TPB>>>(aggP, b2, Wd, bd, out);
}